// round 5
// baseline (speedup 1.0000x reference)
#include <cuda_runtime.h>
#include <cuda_bf16.h>
#include <utility>

// SpeDCT: out[b,:,h,w] = Dinv @ diag(weight[h,w,:]) @ D @ x[b,:,h,w]
// C = 28, H = W = 256, B = 16.
//
// R4: latency-bound profile (DRAM 52.8%, fma 50.1%, occ 41.7%) -> process
// TWO adjacent pixels per thread: float2/LDG.64 loads + STG.64 stores halve
// memory-issue count, two independent accumulator sets double ILP.
// DCT coefficients remain compile-time float immediates (FFMA-imm, rt=1).

static constexpr int  Cc  = 28;
static constexpr int  HWp = 256 * 256;

// cos(pi * m / 56), exact-to-double via range reduction + Taylor.
__host__ __device__ constexpr double cospi56(int m) {
    int mm = m % 112;
    if (mm < 0) mm += 112;
    if (mm > 56) mm = 112 - mm;
    double x  = 3.141592653589793238462643383279502884 * (double)mm / 56.0;
    double x2 = x * x, t = 1.0, s = 1.0;
    for (int i = 1; i <= 24; ++i) { t *= -x2 / (double)((2 * i - 1) * (2 * i)); s += t; }
    return s;
}

// Forward DCT-II entry: D[k][n] = 2*cos(pi*(2n+1)k/56)
template <int k, int n>
__device__ __forceinline__ float cD() {
    constexpr float v = (float)(2.0 * cospi56((2 * n + 1) * k));
    return v;
}
// Inverse entry: Dinv[n][k] = cos(pi*(2n+1)k/56) * (k==0 ? 0.5 : 1.0) / 28
template <int n, int k>
__device__ __forceinline__ float cDI() {
    constexpr float v = (float)(cospi56((2 * n + 1) * k) * ((k == 0) ? 0.5 : 1.0) / 28.0);
    return v;
}

// Stage 1 inner: accumulate all 28 bins for both pixels for pair index n.
// Even k uses (x_n + x_{27-n}), odd k uses (x_n - x_{27-n}).
template <int n, int... ks>
__device__ __forceinline__ void s1_acc2(float (&xd0)[Cc], float (&xd1)[Cc],
                                        float s0, float d0, float s1, float d1,
                                        std::integer_sequence<int, ks...>) {
    (((xd0[ks] = fmaf(((ks & 1) ? d0 : s0), cD<ks, n>(), xd0[ks])),
      (xd1[ks] = fmaf(((ks & 1) ? d1 : s1), cD<ks, n>(), xd1[ks]))), ...);
}

template <int... ns>
__device__ __forceinline__ void stage1(float (&xd0)[Cc], float (&xd1)[Cc],
                                       const float* __restrict__ xp,
                                       std::integer_sequence<int, ns...>) {
    (([&] {
         float2 xa = *reinterpret_cast<const float2*>(xp + (size_t)ns * HWp);
         float2 xb = *reinterpret_cast<const float2*>(xp + (size_t)(27 - ns) * HWp);
         s1_acc2<ns>(xd0, xd1, xa.x + xb.x, xa.x - xb.x, xa.y + xb.y, xa.y - xb.y,
                     std::make_integer_sequence<int, Cc>{});
     }()),
     ...);
}

// Stage 2 dots: even-k / odd-k partial sums.
template <int n, int... js>
__device__ __forceinline__ float dotE(const float (&xd)[Cc],
                                      std::integer_sequence<int, js...>) {
    float e = 0.f;
    ((e = fmaf(xd[2 * js], cDI<n, 2 * js>(), e)), ...);
    return e;
}
template <int n, int... js>
__device__ __forceinline__ float dotO(const float (&xd)[Cc],
                                      std::integer_sequence<int, js...>) {
    float o = 0.f;
    ((o = fmaf(xd[2 * js + 1], cDI<n, 2 * js + 1>(), o)), ...);
    return o;
}

template <int... ns>
__device__ __forceinline__ void stage2(const float (&xd0)[Cc], const float (&xd1)[Cc],
                                       float* __restrict__ op,
                                       std::integer_sequence<int, ns...>) {
    (([&] {
         float E0 = dotE<ns>(xd0, std::make_integer_sequence<int, 14>{});
         float O0 = dotO<ns>(xd0, std::make_integer_sequence<int, 14>{});
         float E1 = dotE<ns>(xd1, std::make_integer_sequence<int, 14>{});
         float O1 = dotO<ns>(xd1, std::make_integer_sequence<int, 14>{});
         *reinterpret_cast<float2*>(op + (size_t)ns * HWp) =
             make_float2(E0 + O0, E1 + O1);
         *reinterpret_cast<float2*>(op + (size_t)(27 - ns) * HWp) =
             make_float2(E0 - O0, E1 - O1);
     }()),
     ...);
}

__global__ void __launch_bounds__(256, 2)
spedct_kernel(const float* __restrict__ x, const float* __restrict__ w,
              float* __restrict__ out) {
    const int pair = blockIdx.y * blockDim.x + threadIdx.x;  // 0..32767
    const int hw   = pair * 2;                               // even -> float2 aligned
    const int b    = blockIdx.x;                             // fastest -> weight L2 reuse

    const float* xp = x + (size_t)b * Cc * HWp + hw;
    float*       op = out + (size_t)b * Cc * HWp + hw;

    float xd0[Cc], xd1[Cc];
#pragma unroll
    for (int k = 0; k < Cc; ++k) { xd0[k] = 0.f; xd1[k] = 0.f; }

    // Forward DCT along channels for both pixels (folded, 2x392 FMA)
    stage1(xd0, xd1, xp, std::make_integer_sequence<int, 14>{});

    // Per-pixel spectral filter. weight rows are 112B each -> 16B aligned.
    const float4* wv0 = reinterpret_cast<const float4*>(w + (size_t)hw * Cc);
    const float4* wv1 = reinterpret_cast<const float4*>(w + (size_t)(hw + 1) * Cc);
#pragma unroll
    for (int j = 0; j < 7; ++j) {
        float4 a = wv0[j], c = wv1[j];
        xd0[4 * j + 0] *= a.x;  xd1[4 * j + 0] *= c.x;
        xd0[4 * j + 1] *= a.y;  xd1[4 * j + 1] *= c.y;
        xd0[4 * j + 2] *= a.z;  xd1[4 * j + 2] *= c.z;
        xd0[4 * j + 3] *= a.w;  xd1[4 * j + 3] *= c.w;
    }

    // Inverse DCT along channels (folded) + 64-bit stores
    stage2(xd0, xd1, op, std::make_integer_sequence<int, 14>{});
}

extern "C" void kernel_launch(void* const* d_in, const int* in_sizes, int n_in,
                              void* d_out, int out_size) {
    const float* x = (const float*)d_in[0];   // [16, 28, 256, 256] f32
    const float* w = (const float*)d_in[1];   // [256, 256, 28] f32
    float*     out = (float*)d_out;           // [16, 28, 256, 256] f32

    dim3 grid(16, HWp / (256 * 2));  // (16, 128); batch fastest for weight L2 reuse
    spedct_kernel<<<grid, 256>>>(x, w, out);
}

// round 6
// speedup vs baseline: 1.0573x; 1.0573x over previous
#include <cuda_runtime.h>
#include <cuda_bf16.h>
#include <utility>

// SpeDCT: out[b,:,h,w] = Dinv @ diag(weight[h,w,:]) @ D @ x[b,:,h,w]
// C = 28, H = W = 256, B = 16.
//
// R6: occupancy-limited latency-bound (R5 ILP experiment regressed).
// 1 pixel/thread (R4 structure) + 48-reg cap (launch_bounds 256,5 ->
// 1280 thr/SM, 62.5% occ) + dead-init elimination + streaming cache hints.
// DCT coefficients are compile-time float immediates (FFMA-imm, rt_SMSP=1).
// DCT symmetry halves FMA count: ~784 FMA/pixel.

static constexpr int  Cc  = 28;
static constexpr int  HWp = 256 * 256;

// cos(pi * m / 56), exact-to-double via range reduction + Taylor.
__host__ __device__ constexpr double cospi56(int m) {
    int mm = m % 112;
    if (mm < 0) mm += 112;
    if (mm > 56) mm = 112 - mm;
    double x  = 3.141592653589793238462643383279502884 * (double)mm / 56.0;
    double x2 = x * x, t = 1.0, s = 1.0;
    for (int i = 1; i <= 24; ++i) { t *= -x2 / (double)((2 * i - 1) * (2 * i)); s += t; }
    return s;
}

// Forward DCT-II entry: D[k][n] = 2*cos(pi*(2n+1)k/56)
template <int k, int n>
__device__ __forceinline__ float cD() {
    constexpr float v = (float)(2.0 * cospi56((2 * n + 1) * k));
    return v;
}
// Inverse entry: Dinv[n][k] = cos(pi*(2n+1)k/56) * (k==0 ? 0.5 : 1.0) / 28
template <int n, int k>
__device__ __forceinline__ float cDI() {
    constexpr float v = (float)(cospi56((2 * n + 1) * k) * ((k == 0) ? 0.5 : 1.0) / 28.0);
    return v;
}

// Stage 1, n == 0: initialize accumulators with a MUL (no zero-init FMA).
template <int... ks>
__device__ __forceinline__ void s1_init(float (&xd)[Cc], float s, float d,
                                        std::integer_sequence<int, ks...>) {
    ((xd[ks] = ((ks & 1) ? d : s) * cD<ks, 0>()), ...);
}

// Stage 1, n >= 1: accumulate. Even k uses s = x_n + x_{27-n}, odd k uses d.
template <int n, int... ks>
__device__ __forceinline__ void s1_acc(float (&xd)[Cc], float s, float d,
                                       std::integer_sequence<int, ks...>) {
    ((xd[ks] = fmaf(((ks & 1) ? d : s), cD<ks, n>(), xd[ks])), ...);
}

template <int... ns>
__device__ __forceinline__ void stage1(float (&xd)[Cc], const float* __restrict__ xp,
                                       std::integer_sequence<int, ns...>) {
    (([&] {
         // streaming loads: x has zero reuse; keep L2 for the weight tensor
         float xa = __ldcs(xp + (size_t)ns * HWp);
         float xb = __ldcs(xp + (size_t)(27 - ns) * HWp);
         if constexpr (ns == 0)
             s1_init(xd, xa + xb, xa - xb, std::make_integer_sequence<int, Cc>{});
         else
             s1_acc<ns>(xd, xa + xb, xa - xb, std::make_integer_sequence<int, Cc>{});
     }()),
     ...);
}

// Stage 2 partial dots: first term is a MUL, remaining 13 are FMA.
template <int n, int... js>
__device__ __forceinline__ float dotE(const float (&xd)[Cc],
                                      std::integer_sequence<int, js...>) {
    float e = xd[0] * cDI<n, 0>();
    ((e = fmaf(xd[2 * (js + 1)], cDI<n, 2 * (js + 1)>(), e)), ...);
    return e;
}
template <int n, int... js>
__device__ __forceinline__ float dotO(const float (&xd)[Cc],
                                      std::integer_sequence<int, js...>) {
    float o = xd[1] * cDI<n, 1>();
    ((o = fmaf(xd[2 * (js + 1) + 1], cDI<n, 2 * (js + 1) + 1>(), o)), ...);
    return o;
}

template <int... ns>
__device__ __forceinline__ void stage2(const float (&xd)[Cc], float* __restrict__ op,
                                       std::integer_sequence<int, ns...>) {
    (([&] {
         float E = dotE<ns>(xd, std::make_integer_sequence<int, 13>{});
         float O = dotO<ns>(xd, std::make_integer_sequence<int, 13>{});
         __stcs(op + (size_t)ns * HWp,        E + O);
         __stcs(op + (size_t)(27 - ns) * HWp, E - O);
     }()),
     ...);
}

__global__ void __launch_bounds__(256, 5)   // cap regs at 48 -> 1280 thr/SM
spedct_kernel(const float* __restrict__ x, const float* __restrict__ w,
              float* __restrict__ out) {
    const int hw = blockIdx.y * blockDim.x + threadIdx.x;  // 0..65535
    const int b  = blockIdx.x;                             // fastest -> weight L2 reuse

    const float* xp = x + (size_t)b * Cc * HWp + hw;
    float*       op = out + (size_t)b * Cc * HWp + hw;

    float xd[Cc];

    // Forward DCT along channels (folded; n=0 initializes via MUL)
    stage1(xd, xp, std::make_integer_sequence<int, 14>{});

    // Per-pixel spectral filter. weight rows are 112B each -> 16B aligned.
    const float4* wv = reinterpret_cast<const float4*>(w + (size_t)hw * Cc);
#pragma unroll
    for (int j = 0; j < 7; ++j) {
        float4 w4 = wv[j];
        xd[4 * j + 0] *= w4.x;
        xd[4 * j + 1] *= w4.y;
        xd[4 * j + 2] *= w4.z;
        xd[4 * j + 3] *= w4.w;
    }

    // Inverse DCT along channels (folded) + streaming stores
    stage2(xd, op, std::make_integer_sequence<int, 14>{});
}

extern "C" void kernel_launch(void* const* d_in, const int* in_sizes, int n_in,
                              void* d_out, int out_size) {
    const float* x = (const float*)d_in[0];   // [16, 28, 256, 256] f32
    const float* w = (const float*)d_in[1];   // [256, 256, 28] f32
    float*     out = (float*)d_out;           // [16, 28, 256, 256] f32

    dim3 grid(16, HWp / 256);  // batch fastest: 16 adjacent blocks share weight slice in L2
    spedct_kernel<<<grid, 256>>>(x, w, out);
}